// round 5
// baseline (speedup 1.0000x reference)
#include <cuda_runtime.h>
#include <cuda_bf16.h>
#include <cstdint>
#include <math.h>

// SimCLR InfoNCE + ranking metrics via mma.sync bf16 split GEMM (sm_103-safe PTX).
//   fn = normalize(concat(feats1, feats2))  [8192, 512] fp32
//   fn = hi + lo (bf16);  sim = hi*hi^T + hi*lo^T + lo*hi^T  (fp32 accum)
//   Lower-triangle 128x128 tiles only; off-diag tiles feed row+col partials.
//   R5: term-inner loop — one stage holds {Ahi,Alo,Bhi,Blo} for a BK=32 chunk,
//   all 3 terms computed per stage. 16 iters, 1 barrier each, 96 MMA/barrier.

namespace {
constexpr int   N      = 8192;
constexpr int   D      = 512;
constexpr int   HALF   = 4096;
constexpr float TEMP   = 0.07f;
constexpr int   BM     = 128;
constexpr int   BK     = 32;
constexpr int   KCH    = 16;             // 512 / 32 k-chunks
constexpr int   STAGES = 3;
constexpr int   LDK    = 40;             // bf16 row stride (80B, conflict-free)
constexpr int   MBUF   = BM * LDK * 2;   // 10240 B per matrix
constexpr int   STAGEB = 4 * MBUF;       // 40960 B per stage
constexpr int   SMEM_DYN = STAGES * STAGEB;  // 122880
constexpr int   NTILES = 64 * 65 / 2;
}

// ---- device scratch ----
__device__ float          g_fn[N * D];
__device__ __nv_bfloat16  g_hi[N * D];
__device__ __nv_bfloat16  g_lo[N * D];
__device__ float          g_pos[N];
__device__ float          g_rowS[N];
__device__ int            g_rowC[N];
__device__ double         g_nll;
__device__ int            g_top1;
__device__ int            g_top5;
__device__ unsigned long long g_rank;

__device__ __forceinline__ uint32_t smem_u32(const void* p) {
    uint32_t a;
    asm("{ .reg .u64 t; cvta.to.shared.u64 t, %1; cvt.u32.u64 %0, t; }" : "=r"(a) : "l"(p));
    return a;
}
#define CP16(sa, g) asm volatile("cp.async.cg.shared.global [%0], [%1], 16;" :: "r"(sa), "l"(g))
#define CP_COMMIT() asm volatile("cp.async.commit_group;")
#define CP_WAIT(n)  asm volatile("cp.async.wait_group %0;" :: "n"(n))
#define LDSM4(r0, r1, r2, r3, a)                                             \
    asm volatile("ldmatrix.sync.aligned.m8n8.x4.shared.b16 {%0,%1,%2,%3}, [%4];" \
                 : "=r"(r0), "=r"(r1), "=r"(r2), "=r"(r3) : "r"(a))
#define MMA16816(c, a, b0, b1)                                               \
    asm volatile("mma.sync.aligned.m16n8k16.row.col.f32.bf16.bf16.f32 "      \
                 "{%0,%1,%2,%3}, {%4,%5,%6,%7}, {%8,%9}, {%0,%1,%2,%3};"     \
                 : "+f"((c)[0]), "+f"((c)[1]), "+f"((c)[2]), "+f"((c)[3])    \
                 : "r"((a)[0]), "r"((a)[1]), "r"((a)[2]), "r"((a)[3]),       \
                   "r"(b0), "r"(b1))

// ---------------- small kernels ----------------
__global__ void k_zero() {
    int i = blockIdx.x * 256 + threadIdx.x;
    g_rowS[i] = 0.f; g_rowC[i] = 0;
    if (i == 0) { g_nll = 0.0; g_top1 = 0; g_top5 = 0; g_rank = 0ull; }
}

__global__ void k_norm(const float* __restrict__ f1, const float* __restrict__ f2) {
    const int row = blockIdx.x;
    const float* src = (row < HALF) ? (f1 + (size_t)row * D)
                                    : (f2 + (size_t)(row - HALF) * D);
    const int t = threadIdx.x;   // 128 threads x float4
    float4 v = reinterpret_cast<const float4*>(src)[t];
    float ss = v.x * v.x + v.y * v.y + v.z * v.z + v.w * v.w;
#pragma unroll
    for (int o = 16; o; o >>= 1) ss += __shfl_xor_sync(0xffffffffu, ss, o);
    __shared__ float ws[4];
    if ((t & 31) == 0) ws[t >> 5] = ss;
    __syncthreads();
    const float inv = 1.0f / fmaxf(sqrtf(ws[0] + ws[1] + ws[2] + ws[3]), 1e-8f);
    float x[4] = { v.x * inv, v.y * inv, v.z * inv, v.w * inv };
    reinterpret_cast<float4*>(g_fn + (size_t)row * D)[t] =
        make_float4(x[0], x[1], x[2], x[3]);
    size_t base = (size_t)row * D + t * 4;
#pragma unroll
    for (int c = 0; c < 4; c++) {
        __nv_bfloat16 h = __float2bfloat16(x[c]);
        g_hi[base + c] = h;
        g_lo[base + c] = __float2bfloat16(x[c] - __bfloat162float(h));
    }
}

__global__ void k_pos() {
    const int row  = blockIdx.x * 8 + (threadIdx.x >> 5);
    const int lane = threadIdx.x & 31;
    const int prow = (row + HALF) & (N - 1);
    const float4* a = reinterpret_cast<const float4*>(g_fn + (size_t)row * D);
    const float4* b = reinterpret_cast<const float4*>(g_fn + (size_t)prow * D);
    float s = 0.f;
#pragma unroll
    for (int q = 0; q < 4; q++) {
        float4 x = a[lane + q * 32], y = b[lane + q * 32];
        s += x.x * y.x + x.y * y.y + x.z * y.z + x.w * y.w;
    }
#pragma unroll
    for (int o = 16; o; o >>= 1) s += __shfl_xor_sync(0xffffffffu, s, o);
    if (lane == 0) g_pos[row] = s;
}

// ---------------- main: triangular-tile HMMA GEMM + fused epilogue ----------------
__global__ void __launch_bounds__(256) k_main() {
    extern __shared__ __align__(16) char dsm[];

    // decode lower-triangle tile (bi >= bj)
    const int t = blockIdx.x;
    int bi = (int)((sqrtf(8.0f * (float)t + 1.0f) - 1.0f) * 0.5f);
    while ((bi + 1) * (bi + 2) / 2 <= t) ++bi;
    while (bi * (bi + 1) / 2 > t) --bi;
    const int bj = t - bi * (bi + 1) / 2;
    const bool offd = (bi != bj);
    const int rowBase = bi * BM;
    const int colBase = bj * BM;

    const int tid  = threadIdx.x;
    const int l    = tid & 31;
    const int wid  = tid >> 5;
    const int warpM = wid & 1;    // 2 -> 64 rows
    const int warpN = wid >> 1;   // 4 -> 32 cols
    const float invT = 1.0f / TEMP;

    // stage base addresses: [Ahi | Alo | Bhi | Blo] per stage
    uint32_t stU[STAGES];
#pragma unroll
    for (int s = 0; s < STAGES; s++) stU[s] = smem_u32(dsm + s * STAGEB);

    // cp.async destination: 2 chunks of 16B per matrix per thread
    uint32_t dstOff[2];
    int gRow[2], gQ[2];
#pragma unroll
    for (int i = 0; i < 2; i++) {
        int c = i * 256 + tid;
        gRow[i] = c >> 2; gQ[i] = c & 3;
        dstOff[i] = (uint32_t)(gRow[i] * (LDK * 2) + gQ[i] * 16);
    }

    const uint32_t aFragOff =
        (uint32_t)(((warpM * 64 + (l & 15)) * LDK + (l >> 4) * 8) * 2);
    const uint32_t bFragOff =
        (uint32_t)(((warpN * 32 + (l & 7) + (l >> 4) * 8) * LDK + ((l >> 3) & 1) * 8) * 2);

    float acc[4][4][4];
#pragma unroll
    for (int mt = 0; mt < 4; mt++)
#pragma unroll
        for (int nt = 0; nt < 4; nt++)
#pragma unroll
            for (int r = 0; r < 4; r++) acc[mt][nt][r] = 0.f;

    // issue one BK=32 chunk (all 4 matrices) into stage b
    auto issue = [&](int k, int b) {
        const int kb = k * BK;
        const uint32_t u = stU[b];
#pragma unroll
        for (int i = 0; i < 2; i++) {
            size_t offA = (size_t)(rowBase + gRow[i]) * D + kb + gQ[i] * 8;
            size_t offB = (size_t)(colBase + gRow[i]) * D + kb + gQ[i] * 8;
            CP16(u + dstOff[i],            g_hi + offA);
            CP16(u + MBUF + dstOff[i],     g_lo + offA);
            CP16(u + 2 * MBUF + dstOff[i], g_hi + offB);
            CP16(u + 3 * MBUF + dstOff[i], g_lo + offB);
        }
    };

    issue(0, 0); CP_COMMIT();
    issue(1, 1); CP_COMMIT();

    for (int g = 0; g < KCH; ++g) {
        const uint32_t u = stU[g % STAGES];
        CP_WAIT(1);
        __syncthreads();
        // refill the stage read 2 iters ago (all warps passed the barrier)
        if (g + 2 < KCH) issue(g + 2, (g + 2) % STAGES);
        CP_COMMIT();

#pragma unroll
        for (int ks = 0; ks < 2; ks++) {
            uint32_t bfrH[2][4], bfrL[2][4];
#pragma unroll
            for (int np = 0; np < 2; np++) {
                uint32_t bo = bFragOff + (uint32_t)(np * 16 * LDK * 2 + ks * 32);
                LDSM4(bfrH[np][0], bfrH[np][1], bfrH[np][2], bfrH[np][3], u + 2 * MBUF + bo);
                LDSM4(bfrL[np][0], bfrL[np][1], bfrL[np][2], bfrL[np][3], u + 3 * MBUF + bo);
            }
#pragma unroll
            for (int mt = 0; mt < 4; mt++) {
                uint32_t ao = aFragOff + (uint32_t)(mt * 16 * LDK * 2 + ks * 32);
                uint32_t aH[4], aL[4];
                LDSM4(aH[0], aH[1], aH[2], aH[3], u + ao);
                LDSM4(aL[0], aL[1], aL[2], aL[3], u + MBUF + ao);
#pragma unroll
                for (int nt = 0; nt < 4; nt++) {
                    uint32_t h0 = bfrH[nt >> 1][(nt & 1) * 2];
                    uint32_t h1 = bfrH[nt >> 1][(nt & 1) * 2 + 1];
                    uint32_t l0 = bfrL[nt >> 1][(nt & 1) * 2];
                    uint32_t l1 = bfrL[nt >> 1][(nt & 1) * 2 + 1];
                    MMA16816(acc[mt][nt], aH, h0, h1);   // hi*hi
                    MMA16816(acc[mt][nt], aH, l0, l1);   // hi*lo
                    MMA16816(acc[mt][nt], aL, h0, h1);   // lo*hi
                }
            }
        }
    }

    // ---- fused epilogue ----
    float pvR[4][2]; int piR[4][2];
    float pvC[4][2]; int piC[4][2];
    float sR[4][2], sC[4][2];
    int   cR[4][2], cC[4][2];
#pragma unroll
    for (int mt = 0; mt < 4; mt++)
#pragma unroll
        for (int h = 0; h < 2; h++) {
            int row = rowBase + warpM * 64 + mt * 16 + (l >> 2) + h * 8;
            pvR[mt][h] = g_pos[row]; piR[mt][h] = (row + HALF) & (N - 1);
            sR[mt][h] = 0.f; cR[mt][h] = 0;
        }
#pragma unroll
    for (int nt = 0; nt < 4; nt++)
#pragma unroll
        for (int e = 0; e < 2; e++) {
            int col = colBase + warpN * 32 + nt * 8 + (l & 3) * 2 + e;
            pvC[nt][e] = g_pos[col]; piC[nt][e] = (col + HALF) & (N - 1);
            sC[nt][e] = 0.f; cC[nt][e] = 0;
        }

#pragma unroll
    for (int mt = 0; mt < 4; mt++)
#pragma unroll
        for (int nt = 0; nt < 4; nt++)
#pragma unroll
            for (int r = 0; r < 4; r++) {
                const int h = r >> 1, e = r & 1;
                const int row = rowBase + warpM * 64 + mt * 16 + (l >> 2) + h * 8;
                const int col = colBase + warpN * 32 + nt * 8 + (l & 3) * 2 + e;
                const float sim = acc[mt][nt][r];
                const float ex  = __expf((sim - 1.0f) * invT);
                if (col != row) {
                    sR[mt][h] += ex;
                    if (col != piR[mt][h] && sim > pvR[mt][h]) cR[mt][h]++;
                }
                if (offd) {
                    sC[nt][e] += ex;
                    if (row != piC[nt][e] && sim > pvC[nt][e]) cC[nt][e]++;
                }
            }

#pragma unroll
    for (int mt = 0; mt < 4; mt++)
#pragma unroll
        for (int h = 0; h < 2; h++) {
            float s = sR[mt][h]; int c = cR[mt][h];
            s += __shfl_xor_sync(0xffffffffu, s, 1);
            s += __shfl_xor_sync(0xffffffffu, s, 2);
            c += __shfl_xor_sync(0xffffffffu, c, 1);
            c += __shfl_xor_sync(0xffffffffu, c, 2);
            if ((l & 3) == 0) {
                int row = rowBase + warpM * 64 + mt * 16 + (l >> 2) + h * 8;
                atomicAdd(&g_rowS[row], s);
                atomicAdd(&g_rowC[row], c);
            }
        }
    if (offd) {
#pragma unroll
        for (int nt = 0; nt < 4; nt++)
#pragma unroll
            for (int e = 0; e < 2; e++) {
                float s = sC[nt][e]; int c = cC[nt][e];
                s += __shfl_xor_sync(0xffffffffu, s, 4);
                s += __shfl_xor_sync(0xffffffffu, s, 8);
                s += __shfl_xor_sync(0xffffffffu, s, 16);
                c += __shfl_xor_sync(0xffffffffu, c, 4);
                c += __shfl_xor_sync(0xffffffffu, c, 8);
                c += __shfl_xor_sync(0xffffffffu, c, 16);
                if (l < 4) {
                    int col = colBase + warpN * 32 + nt * 8 + (l & 3) * 2 + e;
                    atomicAdd(&g_rowS[col], s);
                    atomicAdd(&g_rowC[col], c);
                }
            }
    }
}

__global__ void k_merge() {
    const int row = blockIdx.x * 256 + threadIdx.x;
    const float invT = 1.0f / TEMP;
    const float sv = g_rowS[row];
    const int   cv = g_rowC[row];
    const float term = (logf(sv) + invT) - g_pos[row] * invT;
    float wterm = term;
    int wt1 = (cv == 0) ? 1 : 0;
    int wt5 = (cv < 5) ? 1 : 0;
    long long wr = cv;
#pragma unroll
    for (int o = 16; o; o >>= 1) {
        wterm += __shfl_xor_sync(0xffffffffu, wterm, o);
        wt1   += __shfl_xor_sync(0xffffffffu, wt1, o);
        wt5   += __shfl_xor_sync(0xffffffffu, wt5, o);
        wr    += __shfl_xor_sync(0xffffffffu, wr, o);
    }
    __shared__ double s_term[8];
    __shared__ int s_t1[8], s_t5[8];
    __shared__ unsigned long long s_r[8];
    const int lane = threadIdx.x & 31, w = threadIdx.x >> 5;
    if (lane == 0) { s_term[w] = (double)wterm; s_t1[w] = wt1; s_t5[w] = wt5; s_r[w] = (unsigned long long)wr; }
    __syncthreads();
    if (threadIdx.x == 0) {
        double a = 0.0; int b = 0, c = 0; unsigned long long d2 = 0ull;
#pragma unroll
        for (int i = 0; i < 8; i++) { a += s_term[i]; b += s_t1[i]; c += s_t5[i]; d2 += s_r[i]; }
        atomicAdd(&g_nll, a);
        atomicAdd(&g_top1, b);
        atomicAdd(&g_top5, c);
        atomicAdd(&g_rank, d2);
    }
}

__global__ void k_final(float* __restrict__ out) {
    out[0] = (float)(g_nll / (double)N);
    out[1] = (float)g_top1 / (float)N;
    out[2] = (float)g_top5 / (float)N;
    out[3] = 1.0f + (float)((double)g_rank / (double)N);
}

extern "C" void kernel_launch(void* const* d_in, const int* in_sizes, int n_in,
                              void* d_out, int out_size) {
    (void)in_sizes; (void)n_in; (void)out_size;
    const float* f1 = (const float*)d_in[0];
    const float* f2 = (const float*)d_in[1];
    float* out = (float*)d_out;

    cudaFuncSetAttribute(k_main, cudaFuncAttributeMaxDynamicSharedMemorySize, SMEM_DYN);

    k_zero<<<N / 256, 256>>>();
    k_norm<<<N, 128>>>(f1, f2);
    k_pos<<<N / 8, 256>>>();
    k_main<<<NTILES, 256, SMEM_DYN>>>();
    k_merge<<<N / 256, 256>>>();
    k_final<<<1, 1>>>(out);
}